// round 4
// baseline (speedup 1.0000x reference)
#include <cuda_runtime.h>

// VectorKuramoto factorized:
//   sum_j A*sin(tj - ti - a) = ci*P - si*Q
//   P = sum_j (A cos a) sj - (A sin a) cj ; Q = sum_j (A cos a) cj + (A sin a) sj
// Two-kernel scheme: (1) sincos table -> global scratch (L2-resident),
// (2) barrier-free main kernel, 1 row per warp, small blocks for HW load balance.

namespace {

constexpr int Bb = 4;
constexpr int Nn = 2048;
constexpr int N4 = Nn / 4;              // 512 float4 per row
constexpr int ROWS = Bb * Nn;           // 8192 global rows
constexpr int T1 = 256;                 // table kernel block
constexpr int T2 = 256;                 // main kernel block (8 warps, 8 rows)

typedef unsigned long long ull;

#define FMA2(d, a, b, c) \
    asm("fma.rn.f32x2 %0, %1, %2, %3;" : "=l"(d) : "l"(a), "l"(b), "l"(c))
#define PACK2(d, lo, hi) \
    asm("mov.b64 %0, {%1, %2};" : "=l"(d) : "f"(lo), "f"(hi))
#define UNPACK2(lo, hi, s) \
    asm("mov.b64 {%0, %1}, %2;" : "=f"(lo), "=f"(hi) : "l"(s))

union F4U { float4 v; ull u[2]; };

__device__ __forceinline__ void cell(float A, float a,
                                     ull sj01, ull sj23, ull cj01, ull cj23,
                                     ull& Pa, ull& Pb, ull& Qa, ull& Qb)
{
    float sa, ca;
    __sincosf(a, &sa, &ca);
    float w1 = A * ca;
    float w2 = A * sa;
    float nw2 = -w2;
    ull pw1, pw2, pnw2;
    PACK2(pw1, w1, w1);
    PACK2(pw2, w2, w2);
    PACK2(pnw2, nw2, nw2);
    FMA2(Pa, pnw2, cj01, Pa); FMA2(Pa, pw1, sj01, Pa);
    FMA2(Pb, pnw2, cj23, Pb); FMA2(Pb, pw1, sj23, Pb);
    FMA2(Qa, pw2,  sj01, Qa); FMA2(Qa, pw1, cj01, Qa);
    FMA2(Qb, pw2,  sj23, Qb); FMA2(Qb, pw1, cj23, Qb);
}

} // namespace

// Global sincos table: tab[2*r] = sin(theta[r,:]), tab[2*r+1] = cos(theta[r,:])
// r = b*Nn + i. 8192 rows * 32 B = 256 KB (L2-resident scratch).
__device__ float4 g_tab[2 * ROWS];

extern "C" __global__ void __launch_bounds__(T1)
kuramoto_build_table(const float4* __restrict__ theta4)
{
    int r = blockIdx.x * T1 + threadIdx.x;
    if (r < ROWS) {
        float4 th = theta4[r];
        float4 s, c;
        __sincosf(th.x, &s.x, &c.x);
        __sincosf(th.y, &s.y, &c.y);
        __sincosf(th.z, &s.z, &c.z);
        __sincosf(th.w, &s.w, &c.w);
        g_tab[2 * r]     = s;
        g_tab[2 * r + 1] = c;
    }
}

extern "C" __global__ void __launch_bounds__(T2, 4)
vector_kuramoto_kernel(const float4* __restrict__ theta4,
                       const float4* __restrict__ gamma4,
                       const float4* __restrict__ aff4,
                       const float4* __restrict__ alpha4,
                       const float4* __restrict__ omega4,
                       const float4* __restrict__ kappa4,
                       const float4* __restrict__ abias4,
                       float4* __restrict__ out4)
{
    const int warp = threadIdx.x >> 5;
    const int lane = threadIdx.x & 31;

    const int row = blockIdx.x * 8 + warp;      // global row r = b*Nn + i
    const int b   = row >> 11;
    const int i   = row & (Nn - 1);

    const int rb = row * N4;                    // stream row base (float4)
    const int bb = i * N4;                      // bias row base
    const int tb = (b << 11) * 2;               // table base for batch b (float4)

    ull Pa = 0, Pb = 0, Qa = 0, Qb = 0;

    #pragma unroll 1
    for (int jb0 = lane; jb0 < N4; jb0 += 64) {
        const int jb1 = jb0 + 32;
        // Front-batched stream loads (6x LDG.128, evict-first: zero reuse).
        float4 A0 = __ldcs(aff4   + rb + jb0);
        float4 T0 = __ldcs(alpha4 + rb + jb0);
        float4 A1 = __ldcs(aff4   + rb + jb1);
        float4 T1v = __ldcs(alpha4 + rb + jb1);
        float4 B0 = abias4[bb + jb0];           // 4x reuse across b via L2
        float4 B1 = abias4[bb + jb1];

        {
            const int t0 = tb + (jb0 << 3);     // 4 j's: 8 float4, contiguous
            F4U sj, cj;
            sj.v = g_tab[t0 + 0]; cj.v = g_tab[t0 + 1];
            cell(A0.x, T0.x + B0.x, sj.u[0], sj.u[1], cj.u[0], cj.u[1], Pa, Pb, Qa, Qb);
            sj.v = g_tab[t0 + 2]; cj.v = g_tab[t0 + 3];
            cell(A0.y, T0.y + B0.y, sj.u[0], sj.u[1], cj.u[0], cj.u[1], Pa, Pb, Qa, Qb);
            sj.v = g_tab[t0 + 4]; cj.v = g_tab[t0 + 5];
            cell(A0.z, T0.z + B0.z, sj.u[0], sj.u[1], cj.u[0], cj.u[1], Pa, Pb, Qa, Qb);
            sj.v = g_tab[t0 + 6]; cj.v = g_tab[t0 + 7];
            cell(A0.w, T0.w + B0.w, sj.u[0], sj.u[1], cj.u[0], cj.u[1], Pa, Pb, Qa, Qb);
        }
        {
            const int t1 = tb + (jb1 << 3);
            F4U sj, cj;
            sj.v = g_tab[t1 + 0]; cj.v = g_tab[t1 + 1];
            cell(A1.x, T1v.x + B1.x, sj.u[0], sj.u[1], cj.u[0], cj.u[1], Pa, Pb, Qa, Qb);
            sj.v = g_tab[t1 + 2]; cj.v = g_tab[t1 + 3];
            cell(A1.y, T1v.y + B1.y, sj.u[0], sj.u[1], cj.u[0], cj.u[1], Pa, Pb, Qa, Qb);
            sj.v = g_tab[t1 + 4]; cj.v = g_tab[t1 + 5];
            cell(A1.z, T1v.z + B1.z, sj.u[0], sj.u[1], cj.u[0], cj.u[1], Pa, Pb, Qa, Qb);
            sj.v = g_tab[t1 + 6]; cj.v = g_tab[t1 + 7];
            cell(A1.w, T1v.w + B1.w, sj.u[0], sj.u[1], cj.u[0], cj.u[1], Pa, Pb, Qa, Qb);
        }
    }

    // Warp reduction of the 16 scalar accumulators (8 floats after unpack x2).
    float p[4], q[4];
    UNPACK2(p[0], p[1], Pa); UNPACK2(p[2], p[3], Pb);
    UNPACK2(q[0], q[1], Qa); UNPACK2(q[2], q[3], Qb);

    #pragma unroll
    for (int off = 16; off; off >>= 1) {
        #pragma unroll
        for (int d = 0; d < 4; ++d) {
            p[d] += __shfl_down_sync(0xffffffffu, p[d], off);
            q[d] += __shfl_down_sync(0xffffffffu, q[d], off);
        }
    }

    if (lane == 0) {
        const float inv = 1.0f / (float)Nn;   // COUPLING=1, DT=1
        float4 th = theta4[row];
        float4 si = g_tab[2 * row];
        float4 ci = g_tab[2 * row + 1];
        float4 g  = gamma4[row];
        float4 om = omega4[i];
        float4 kp = kappa4[i];
        float4 o;
        o.x = th.x + om.x + kp.x * (g.x - th.x) + inv * (ci.x * p[0] - si.x * q[0]);
        o.y = th.y + om.y + kp.y * (g.y - th.y) + inv * (ci.y * p[1] - si.y * q[1]);
        o.z = th.z + om.z + kp.z * (g.z - th.z) + inv * (ci.z * p[2] - si.z * q[2]);
        o.w = th.w + om.w + kp.w * (g.w - th.w) + inv * (ci.w * p[3] - si.w * q[3]);
        out4[row] = o;
    }
}

extern "C" void kernel_launch(void* const* d_in, const int* in_sizes, int n_in,
                              void* d_out, int out_size) {
    (void)in_sizes; (void)n_in; (void)out_size;
    const float4* theta4 = (const float4*)d_in[0];
    const float4* gamma4 = (const float4*)d_in[1];
    const float4* aff4   = (const float4*)d_in[2];
    const float4* alpha4 = (const float4*)d_in[3];
    const float4* omega4 = (const float4*)d_in[4];
    const float4* kappa4 = (const float4*)d_in[5];
    const float4* abias4 = (const float4*)d_in[6];
    float4* out4 = (float4*)d_out;

    kuramoto_build_table<<<(ROWS + T1 - 1) / T1, T1>>>(theta4);

    const int grid = ROWS / 8;   // 1024 blocks of 8 warps (1 row per warp)
    vector_kuramoto_kernel<<<grid, T2>>>(
        theta4, gamma4, aff4, alpha4, omega4, kappa4, abias4, out4);
}

// round 5
// speedup vs baseline: 2.4511x; 2.4511x over previous
#include <cuda_runtime.h>

// VectorKuramoto factorized:
//   sum_j A*sin(tj - ti - a) = ci*P - si*Q
//   P = sum_j (A cos a) sj - (A sin a) cj ; Q = sum_j (A cos a) cj + (A sin a) sj
// Two kernels: (1) global sincos tables (separate s/c arrays, L2-resident),
// (2) main: warp owns a row-pair, one j per lane per step -> every load
// (streams scalar, tables float4) is perfectly warp-coalesced. Small 128-thr
// blocks (grid=1024) for fine-grained HW load balance; no barriers anywhere.

namespace {

constexpr int Bb = 4;
constexpr int Nn = 2048;
constexpr int ROWS = Bb * Nn;           // 8192
constexpr int T1 = 256;
constexpr int T2 = 128;                 // 4 warps per block
constexpr int PAIRS_PER_BLOCK = 4;      // 1 row-pair per warp

typedef unsigned long long ull;

#define FMA2(d, a, b, c) \
    asm("fma.rn.f32x2 %0, %1, %2, %3;" : "=l"(d) : "l"(a), "l"(b), "l"(c))
#define PACK2(d, lo, hi) \
    asm("mov.b64 %0, {%1, %2};" : "=l"(d) : "f"(lo), "f"(hi))
#define UNPACK2(lo, hi, s) \
    asm("mov.b64 {%0, %1}, %2;" : "=f"(lo), "=f"(hi) : "l"(s))

union F4U { float4 v; ull u[2]; };

// One (i,j) cell for one row: a = alpha_total, A = affinity.
__device__ __forceinline__ void cell(float A, float a,
                                     ull sj01, ull sj23, ull cj01, ull cj23,
                                     ull& Pa, ull& Pb, ull& Qa, ull& Qb)
{
    float sa, ca;
    __sincosf(a, &sa, &ca);
    float w1 = A * ca;
    float w2 = A * sa;
    float nw2 = -w2;
    ull pw1, pw2, pnw2;
    PACK2(pw1, w1, w1);
    PACK2(pw2, w2, w2);
    PACK2(pnw2, nw2, nw2);
    FMA2(Pa, pnw2, cj01, Pa); FMA2(Pa, pw1, sj01, Pa);
    FMA2(Pb, pnw2, cj23, Pb); FMA2(Pb, pw1, sj23, Pb);
    FMA2(Qa, pw2,  sj01, Qa); FMA2(Qa, pw1, cj01, Qa);
    FMA2(Qb, pw2,  sj23, Qb); FMA2(Qb, pw1, cj23, Qb);
}

} // namespace

// Separate s / c tables so warp reads of either are fully contiguous.
__device__ float4 g_stab[ROWS];
__device__ float4 g_ctab[ROWS];

extern "C" __global__ void __launch_bounds__(T1)
kuramoto_build_table(const float4* __restrict__ theta4)
{
    int r = blockIdx.x * T1 + threadIdx.x;
    if (r < ROWS) {
        float4 th = theta4[r];
        float4 s, c;
        __sincosf(th.x, &s.x, &c.x);
        __sincosf(th.y, &s.y, &c.y);
        __sincosf(th.z, &s.z, &c.z);
        __sincosf(th.w, &s.w, &c.w);
        g_stab[r] = s;
        g_ctab[r] = c;
    }
}

extern "C" __global__ void __launch_bounds__(T2)
vector_kuramoto_kernel(const float4* __restrict__ theta4,
                       const float4* __restrict__ gamma4,
                       const float* __restrict__ aff,
                       const float* __restrict__ alpha,
                       const float4* __restrict__ omega4,
                       const float4* __restrict__ kappa4,
                       const float* __restrict__ abias,
                       float4* __restrict__ out4)
{
    const int warp = threadIdx.x >> 5;
    const int lane = threadIdx.x & 31;

    const int pairid = blockIdx.x * PAIRS_PER_BLOCK + warp; // 0..4095
    const int row0 = pairid * 2;            // global row = b*Nn + i
    const int b    = row0 >> 11;
    const int i0   = row0 & (Nn - 1);

    const int rb0 = row0 * Nn;              // stream row base (floats)
    const int rb1 = rb0 + Nn;
    const int bb0 = i0 * Nn;
    const int bb1 = bb0 + Nn;
    const int tb  = b << 11;                // table base (float4 rows)

    ull P0a = 0, P0b = 0, Q0a = 0, Q0b = 0;
    ull P1a = 0, P1b = 0, Q1a = 0, Q1b = 0;

    #pragma unroll 2
    for (int jc = 0; jc < Nn; jc += 32) {
        const int j = jc + lane;
        // All loads warp-coalesced: streams 128 B/warp, tables 512 B/warp.
        float A0 = __ldcs(aff   + rb0 + j);
        float T0 = __ldcs(alpha + rb0 + j);
        float A1 = __ldcs(aff   + rb1 + j);
        float T1v = __ldcs(alpha + rb1 + j);
        float B0 = abias[bb0 + j];
        float B1 = abias[bb1 + j];
        F4U sj, cj;
        sj.v = g_stab[tb + j];
        cj.v = g_ctab[tb + j];

        cell(A0, T0 + B0, sj.u[0], sj.u[1], cj.u[0], cj.u[1], P0a, P0b, Q0a, Q0b);
        cell(A1, T1v + B1, sj.u[0], sj.u[1], cj.u[0], cj.u[1], P1a, P1b, Q1a, Q1b);
    }

    // Warp reduction (each lane holds partial sums over its j subset).
    float p0[4], q0[4], p1[4], q1[4];
    UNPACK2(p0[0], p0[1], P0a); UNPACK2(p0[2], p0[3], P0b);
    UNPACK2(q0[0], q0[1], Q0a); UNPACK2(q0[2], q0[3], Q0b);
    UNPACK2(p1[0], p1[1], P1a); UNPACK2(p1[2], p1[3], P1b);
    UNPACK2(q1[0], q1[1], Q1a); UNPACK2(q1[2], q1[3], Q1b);

    #pragma unroll
    for (int off = 16; off; off >>= 1) {
        #pragma unroll
        for (int d = 0; d < 4; ++d) {
            p0[d] += __shfl_down_sync(0xffffffffu, p0[d], off);
            q0[d] += __shfl_down_sync(0xffffffffu, q0[d], off);
            p1[d] += __shfl_down_sync(0xffffffffu, p1[d], off);
            q1[d] += __shfl_down_sync(0xffffffffu, q1[d], off);
        }
    }

    if (lane == 0) {
        const float inv = 1.0f / (float)Nn;   // COUPLING=1, DT=1
        {
            const int r = row0;
            const int i = i0;
            float4 th = theta4[r];
            float4 si = g_stab[r];
            float4 ci = g_ctab[r];
            float4 g  = gamma4[r];
            float4 om = omega4[i];
            float4 kp = kappa4[i];
            float4 o;
            o.x = th.x + om.x + kp.x * (g.x - th.x) + inv * (ci.x * p0[0] - si.x * q0[0]);
            o.y = th.y + om.y + kp.y * (g.y - th.y) + inv * (ci.y * p0[1] - si.y * q0[1]);
            o.z = th.z + om.z + kp.z * (g.z - th.z) + inv * (ci.z * p0[2] - si.z * q0[2]);
            o.w = th.w + om.w + kp.w * (g.w - th.w) + inv * (ci.w * p0[3] - si.w * q0[3]);
            out4[r] = o;
        }
        {
            const int r = row0 + 1;
            const int i = i0 + 1;
            float4 th = theta4[r];
            float4 si = g_stab[r];
            float4 ci = g_ctab[r];
            float4 g  = gamma4[r];
            float4 om = omega4[i];
            float4 kp = kappa4[i];
            float4 o;
            o.x = th.x + om.x + kp.x * (g.x - th.x) + inv * (ci.x * p1[0] - si.x * q1[0]);
            o.y = th.y + om.y + kp.y * (g.y - th.y) + inv * (ci.y * p1[1] - si.y * q1[1]);
            o.z = th.z + om.z + kp.z * (g.z - th.z) + inv * (ci.z * p1[2] - si.z * q1[2]);
            o.w = th.w + om.w + kp.w * (g.w - th.w) + inv * (ci.w * p1[3] - si.w * q1[3]);
            out4[r] = o;
        }
    }
}

extern "C" void kernel_launch(void* const* d_in, const int* in_sizes, int n_in,
                              void* d_out, int out_size) {
    (void)in_sizes; (void)n_in; (void)out_size;
    const float4* theta4 = (const float4*)d_in[0];
    const float4* gamma4 = (const float4*)d_in[1];
    const float*  aff    = (const float*)d_in[2];
    const float*  alpha  = (const float*)d_in[3];
    const float4* omega4 = (const float4*)d_in[4];
    const float4* kappa4 = (const float4*)d_in[5];
    const float*  abias  = (const float*)d_in[6];
    float4* out4 = (float4*)d_out;

    kuramoto_build_table<<<(ROWS + T1 - 1) / T1, T1>>>(theta4);

    const int grid = (ROWS / 2) / PAIRS_PER_BLOCK;   // 1024 blocks, 4 warps each
    vector_kuramoto_kernel<<<grid, T2>>>(
        theta4, gamma4, aff, alpha, omega4, kappa4, abias, out4);
}

// round 6
// speedup vs baseline: 3.1944x; 1.3032x over previous
#include <cuda_runtime.h>

// VectorKuramoto factorized:
//   sum_j A*sin(tj - ti - a) = ci*P - si*Q
//   P = sum_j (A cos a) sj - (A sin a) cj ; Q = sum_j (A cos a) cj + (A sin a) sj
// R2 memory structure (smem sincos tables, float4 j-chunks, barrier-free
// mainloop) + exact one-wave grid: 4 batch-groups x (nsm/2) CTAs = 2 CTAs/SM,
// rows assigned at warp granularity across each group (~4% residual skew).

namespace {

constexpr int Bb = 4;
constexpr int Nn = 2048;
constexpr int N4 = Nn / 4;              // 512 float4 per row
constexpr int THREADS = 256;            // 8 warps

__device__ __host__ __forceinline__ int padidx(int i) { return i + (i >> 3); }
constexpr int PAD_N = Nn + (Nn >> 3);   // 2304 float4 slots per table
constexpr int SMEM_BYTES = 2 * PAD_N * (int)sizeof(float4);  // 73728 B

typedef unsigned long long ull;

#define FMA2(d, a, b, c) \
    asm("fma.rn.f32x2 %0, %1, %2, %3;" : "=l"(d) : "l"(a), "l"(b), "l"(c))
#define PACK2(d, lo, hi) \
    asm("mov.b64 %0, {%1, %2};" : "=l"(d) : "f"(lo), "f"(hi))
#define UNPACK2(lo, hi, s) \
    asm("mov.b64 {%0, %1}, %2;" : "=f"(lo), "=f"(hi) : "l"(s))

union F4U { float4 v; ull u[2]; };

__device__ __forceinline__ void cell(float A, float a,
                                     ull sj01, ull sj23, ull cj01, ull cj23,
                                     ull& Pa, ull& Pb, ull& Qa, ull& Qb)
{
    float sa, ca;
    __sincosf(a, &sa, &ca);
    float w1 = A * ca;
    float w2 = A * sa;
    float nw2 = -w2;
    ull pw1, pw2, pnw2;
    PACK2(pw1, w1, w1);
    PACK2(pw2, w2, w2);
    PACK2(pnw2, nw2, nw2);
    FMA2(Pa, pnw2, cj01, Pa); FMA2(Pa, pw1, sj01, Pa);
    FMA2(Pb, pnw2, cj23, Pb); FMA2(Pb, pw1, sj23, Pb);
    FMA2(Qa, pw2,  sj01, Qa); FMA2(Qa, pw1, cj01, Qa);
    FMA2(Qb, pw2,  sj23, Qb); FMA2(Qb, pw1, cj23, Qb);
}

} // namespace

extern "C" __global__ void __launch_bounds__(THREADS, 2)
vector_kuramoto_kernel(const float4* __restrict__ theta4,
                       const float4* __restrict__ gamma4,
                       const float4* __restrict__ aff4,
                       const float4* __restrict__ alpha4,
                       const float4* __restrict__ omega4,
                       const float4* __restrict__ kappa4,
                       const float4* __restrict__ abias4,
                       float4* __restrict__ out4)
{
    extern __shared__ float4 smem[];
    float4* s4 = smem;            // sin(theta[b,r,:]) at padidx(r)
    float4* c4 = smem + PAD_N;    // cos(theta[b,r,:]) at padidx(r)

    const int K = gridDim.x >> 2;            // CTAs per batch-group
    const int b    = blockIdx.x & 3;         // batch for this CTA
    const int rank = blockIdx.x >> 2;        // rank within group, 0..K-1

    const int tid  = threadIdx.x;
    const int warp = tid >> 5;
    const int lane = tid & 31;

    // Build per-batch sincos table (theta[b,r,:] is one float4, D=4).
    for (int r = tid; r < Nn; r += THREADS) {
        float4 th = theta4[b * Nn + r];
        float4 s, c;
        __sincosf(th.x, &s.x, &c.x);
        __sincosf(th.y, &s.y, &c.y);
        __sincosf(th.z, &s.z, &c.z);
        __sincosf(th.w, &s.w, &c.w);
        s4[padidx(r)] = s;
        c4[padidx(r)] = c;
    }
    __syncthreads();

    // Warp-granular row assignment: wg = warp*K + rank spreads the +1-row
    // warps across warp-slots (and thus SMSPs) evenly.
    const int wg     = warp * K + rank;      // 0 .. 8K-1
    const int stride = K << 3;               // 8K warps per group
    const float inv  = 1.0f / (float)Nn;     // COUPLING=1, DT=1

    for (int i = wg; i < Nn; i += stride) {
        const int row = b * Nn + i;          // global row
        const int rb  = row * N4;            // stream base (float4)
        const int bb  = i * N4;              // bias base (float4)

        ull Pa = 0, Pb = 0, Qa = 0, Qb = 0;

        #pragma unroll 1
        for (int jb0 = lane; jb0 < N4; jb0 += 64) {
            const int jb1 = jb0 + 32;
            // Front-batched coalesced LDG.128 (streams evict-first).
            float4 A0 = __ldcs(aff4   + rb + jb0);
            float4 T0 = __ldcs(alpha4 + rb + jb0);
            float4 A1 = __ldcs(aff4   + rb + jb1);
            float4 T1 = __ldcs(alpha4 + rb + jb1);
            float4 B0 = abias4[bb + jb0];     // 4x L2 reuse across batches
            float4 B1 = abias4[bb + jb1];

            {
                const int j0 = jb0 << 2;
                F4U sj, cj;
                sj.v = s4[padidx(j0 + 0)]; cj.v = c4[padidx(j0 + 0)];
                cell(A0.x, T0.x + B0.x, sj.u[0], sj.u[1], cj.u[0], cj.u[1], Pa, Pb, Qa, Qb);
                sj.v = s4[padidx(j0 + 1)]; cj.v = c4[padidx(j0 + 1)];
                cell(A0.y, T0.y + B0.y, sj.u[0], sj.u[1], cj.u[0], cj.u[1], Pa, Pb, Qa, Qb);
                sj.v = s4[padidx(j0 + 2)]; cj.v = c4[padidx(j0 + 2)];
                cell(A0.z, T0.z + B0.z, sj.u[0], sj.u[1], cj.u[0], cj.u[1], Pa, Pb, Qa, Qb);
                sj.v = s4[padidx(j0 + 3)]; cj.v = c4[padidx(j0 + 3)];
                cell(A0.w, T0.w + B0.w, sj.u[0], sj.u[1], cj.u[0], cj.u[1], Pa, Pb, Qa, Qb);
            }
            {
                const int j1 = jb1 << 2;
                F4U sj, cj;
                sj.v = s4[padidx(j1 + 0)]; cj.v = c4[padidx(j1 + 0)];
                cell(A1.x, T1.x + B1.x, sj.u[0], sj.u[1], cj.u[0], cj.u[1], Pa, Pb, Qa, Qb);
                sj.v = s4[padidx(j1 + 1)]; cj.v = c4[padidx(j1 + 1)];
                cell(A1.y, T1.y + B1.y, sj.u[0], sj.u[1], cj.u[0], cj.u[1], Pa, Pb, Qa, Qb);
                sj.v = s4[padidx(j1 + 2)]; cj.v = c4[padidx(j1 + 2)];
                cell(A1.z, T1.z + B1.z, sj.u[0], sj.u[1], cj.u[0], cj.u[1], Pa, Pb, Qa, Qb);
                sj.v = s4[padidx(j1 + 3)]; cj.v = c4[padidx(j1 + 3)];
                cell(A1.w, T1.w + B1.w, sj.u[0], sj.u[1], cj.u[0], cj.u[1], Pa, Pb, Qa, Qb);
            }
        }

        // Warp reduction of the 8 scalar accumulators.
        float p[4], q[4];
        UNPACK2(p[0], p[1], Pa); UNPACK2(p[2], p[3], Pb);
        UNPACK2(q[0], q[1], Qa); UNPACK2(q[2], q[3], Qb);

        #pragma unroll
        for (int off = 16; off; off >>= 1) {
            #pragma unroll
            for (int d = 0; d < 4; ++d) {
                p[d] += __shfl_down_sync(0xffffffffu, p[d], off);
                q[d] += __shfl_down_sync(0xffffffffu, q[d], off);
            }
        }

        if (lane == 0) {
            float4 th = theta4[row];
            float4 si = s4[padidx(i)];
            float4 ci = c4[padidx(i)];
            float4 g  = gamma4[row];
            float4 om = omega4[i];
            float4 kp = kappa4[i];
            float4 o;
            o.x = th.x + om.x + kp.x * (g.x - th.x) + inv * (ci.x * p[0] - si.x * q[0]);
            o.y = th.y + om.y + kp.y * (g.y - th.y) + inv * (ci.y * p[1] - si.y * q[1]);
            o.z = th.z + om.z + kp.z * (g.z - th.z) + inv * (ci.z * p[2] - si.z * q[2]);
            o.w = th.w + om.w + kp.w * (g.w - th.w) + inv * (ci.w * p[3] - si.w * q[3]);
            out4[row] = o;
        }
    }
}

extern "C" void kernel_launch(void* const* d_in, const int* in_sizes, int n_in,
                              void* d_out, int out_size) {
    (void)in_sizes; (void)n_in; (void)out_size;
    const float4* theta4 = (const float4*)d_in[0];
    const float4* gamma4 = (const float4*)d_in[1];
    const float4* aff4   = (const float4*)d_in[2];
    const float4* alpha4 = (const float4*)d_in[3];
    const float4* omega4 = (const float4*)d_in[4];
    const float4* kappa4 = (const float4*)d_in[5];
    const float4* abias4 = (const float4*)d_in[6];
    float4* out4 = (float4*)d_out;

    static int nsm = 0;
    if (nsm == 0) {
        cudaDeviceProp prop;
        if (cudaGetDeviceProperties(&prop, 0) == cudaSuccess && prop.multiProcessorCount > 0)
            nsm = prop.multiProcessorCount;
        else
            nsm = 148;
        cudaFuncSetAttribute(vector_kuramoto_kernel,
                             cudaFuncAttributeMaxDynamicSharedMemorySize, SMEM_BYTES);
    }

    const int grid = 4 * (nsm / 2);   // 4 batch-groups, 2 CTAs/SM, one wave
    vector_kuramoto_kernel<<<grid, THREADS, SMEM_BYTES>>>(
        theta4, gamma4, aff4, alpha4, omega4, kappa4, abias4, out4);
}

// round 7
// speedup vs baseline: 3.8271x; 1.1981x over previous
#include <cuda_runtime.h>

// VectorKuramoto factorized:
//   sum_j A*sin(tj - ti - a) = ci*P - si*Q
//   P = sum_j (A cos a) sj - (A sin a) cj ; Q = sum_j (A cos a) cj + (A sin a) sj
// R2 mainloop (smem sincos tables, float4 j-chunks, barrier-free) +
// 512-thread CTAs (32 warps/SM) + exact one-wave grid (2 CTAs/SM) +
// warp-granular row balancing (per-SM row totals flat to ~2%).

namespace {

constexpr int Bb = 4;
constexpr int Nn = 2048;
constexpr int N4 = Nn / 4;              // 512 float4 per row
constexpr int THREADS = 512;            // 16 warps

__device__ __host__ __forceinline__ int padidx(int i) { return i + (i >> 3); }
constexpr int PAD_N = Nn + (Nn >> 3);   // 2304 float4 slots per table
constexpr int SMEM_BYTES = 2 * PAD_N * (int)sizeof(float4);  // 73728 B

typedef unsigned long long ull;

#define FMA2(d, a, b, c) \
    asm("fma.rn.f32x2 %0, %1, %2, %3;" : "=l"(d) : "l"(a), "l"(b), "l"(c))
#define PACK2(d, lo, hi) \
    asm("mov.b64 %0, {%1, %2};" : "=l"(d) : "f"(lo), "f"(hi))
#define UNPACK2(lo, hi, s) \
    asm("mov.b64 {%0, %1}, %2;" : "=f"(lo), "=f"(hi) : "l"(s))

union F4U { float4 v; ull u[2]; };

__device__ __forceinline__ void cell(float A, float a,
                                     ull sj01, ull sj23, ull cj01, ull cj23,
                                     ull& Pa, ull& Pb, ull& Qa, ull& Qb)
{
    float sa, ca;
    __sincosf(a, &sa, &ca);
    float w1 = A * ca;
    float w2 = A * sa;
    float nw2 = -w2;
    ull pw1, pw2, pnw2;
    PACK2(pw1, w1, w1);
    PACK2(pw2, w2, w2);
    PACK2(pnw2, nw2, nw2);
    FMA2(Pa, pnw2, cj01, Pa); FMA2(Pa, pw1, sj01, Pa);
    FMA2(Pb, pnw2, cj23, Pb); FMA2(Pb, pw1, sj23, Pb);
    FMA2(Qa, pw2,  sj01, Qa); FMA2(Qa, pw1, cj01, Qa);
    FMA2(Qb, pw2,  sj23, Qb); FMA2(Qb, pw1, cj23, Qb);
}

} // namespace

extern "C" __global__ void __launch_bounds__(THREADS, 2)
vector_kuramoto_kernel(const float4* __restrict__ theta4,
                       const float4* __restrict__ gamma4,
                       const float4* __restrict__ aff4,
                       const float4* __restrict__ alpha4,
                       const float4* __restrict__ omega4,
                       const float4* __restrict__ kappa4,
                       const float4* __restrict__ abias4,
                       float4* __restrict__ out4)
{
    extern __shared__ float4 smem[];
    float4* s4 = smem;            // sin(theta[b,r,:]) at padidx(r)
    float4* c4 = smem + PAD_N;    // cos(theta[b,r,:]) at padidx(r)

    const int K    = gridDim.x >> 2;     // CTAs per batch-group (nsm/2)
    const int b    = blockIdx.x & 3;     // batch for this CTA
    const int rank = blockIdx.x >> 2;    // rank within group, 0..K-1

    const int tid  = threadIdx.x;
    const int warp = tid >> 5;
    const int lane = tid & 31;

    // Build per-batch sincos table (theta[b,r,:] is one float4, D=4).
    for (int r = tid; r < Nn; r += THREADS) {
        float4 th = theta4[b * Nn + r];
        float4 s, c;
        __sincosf(th.x, &s.x, &c.x);
        __sincosf(th.y, &s.y, &c.y);
        __sincosf(th.z, &s.z, &c.z);
        __sincosf(th.w, &s.w, &c.w);
        s4[padidx(r)] = s;
        c4[padidx(r)] = c;
    }
    __syncthreads();

    // Warp-granular row assignment. wg = warp*K + rank spreads the +1-row
    // warps evenly across CTAs (and SMs).
    const int wg     = warp * K + rank;  // 0 .. 16K-1
    const int stride = K << 4;           // 16K warps per group
    const float inv  = 1.0f / (float)Nn; // COUPLING=1, DT=1

    for (int i = wg; i < Nn; i += stride) {
        const int row = b * Nn + i;
        const int rb  = row * N4;        // stream base (float4)
        const int bb  = i * N4;          // bias base (float4)

        ull Pa = 0, Pb = 0, Qa = 0, Qb = 0;

        #pragma unroll 1
        for (int jb0 = lane; jb0 < N4; jb0 += 64) {
            const int jb1 = jb0 + 32;
            // Front-batched coalesced LDG.128 (streams evict-first).
            float4 A0 = __ldcs(aff4   + rb + jb0);
            float4 T0 = __ldcs(alpha4 + rb + jb0);
            float4 A1 = __ldcs(aff4   + rb + jb1);
            float4 T1 = __ldcs(alpha4 + rb + jb1);
            float4 B0 = abias4[bb + jb0];     // 4x L2 reuse across batches
            float4 B1 = abias4[bb + jb1];

            {
                const int j0 = jb0 << 2;
                F4U sj, cj;
                sj.v = s4[padidx(j0 + 0)]; cj.v = c4[padidx(j0 + 0)];
                cell(A0.x, T0.x + B0.x, sj.u[0], sj.u[1], cj.u[0], cj.u[1], Pa, Pb, Qa, Qb);
                sj.v = s4[padidx(j0 + 1)]; cj.v = c4[padidx(j0 + 1)];
                cell(A0.y, T0.y + B0.y, sj.u[0], sj.u[1], cj.u[0], cj.u[1], Pa, Pb, Qa, Qb);
                sj.v = s4[padidx(j0 + 2)]; cj.v = c4[padidx(j0 + 2)];
                cell(A0.z, T0.z + B0.z, sj.u[0], sj.u[1], cj.u[0], cj.u[1], Pa, Pb, Qa, Qb);
                sj.v = s4[padidx(j0 + 3)]; cj.v = c4[padidx(j0 + 3)];
                cell(A0.w, T0.w + B0.w, sj.u[0], sj.u[1], cj.u[0], cj.u[1], Pa, Pb, Qa, Qb);
            }
            {
                const int j1 = jb1 << 2;
                F4U sj, cj;
                sj.v = s4[padidx(j1 + 0)]; cj.v = c4[padidx(j1 + 0)];
                cell(A1.x, T1.x + B1.x, sj.u[0], sj.u[1], cj.u[0], cj.u[1], Pa, Pb, Qa, Qb);
                sj.v = s4[padidx(j1 + 1)]; cj.v = c4[padidx(j1 + 1)];
                cell(A1.y, T1.y + B1.y, sj.u[0], sj.u[1], cj.u[0], cj.u[1], Pa, Pb, Qa, Qb);
                sj.v = s4[padidx(j1 + 2)]; cj.v = c4[padidx(j1 + 2)];
                cell(A1.z, T1.z + B1.z, sj.u[0], sj.u[1], cj.u[0], cj.u[1], Pa, Pb, Qa, Qb);
                sj.v = s4[padidx(j1 + 3)]; cj.v = c4[padidx(j1 + 3)];
                cell(A1.w, T1.w + B1.w, sj.u[0], sj.u[1], cj.u[0], cj.u[1], Pa, Pb, Qa, Qb);
            }
        }

        // Warp reduction of the 8 scalar accumulators.
        float p[4], q[4];
        UNPACK2(p[0], p[1], Pa); UNPACK2(p[2], p[3], Pb);
        UNPACK2(q[0], q[1], Qa); UNPACK2(q[2], q[3], Qb);

        #pragma unroll
        for (int off = 16; off; off >>= 1) {
            #pragma unroll
            for (int d = 0; d < 4; ++d) {
                p[d] += __shfl_down_sync(0xffffffffu, p[d], off);
                q[d] += __shfl_down_sync(0xffffffffu, q[d], off);
            }
        }

        if (lane == 0) {
            float4 th = theta4[row];
            float4 si = s4[padidx(i)];
            float4 ci = c4[padidx(i)];
            float4 g  = gamma4[row];
            float4 om = omega4[i];
            float4 kp = kappa4[i];
            float4 o;
            o.x = th.x + om.x + kp.x * (g.x - th.x) + inv * (ci.x * p[0] - si.x * q[0]);
            o.y = th.y + om.y + kp.y * (g.y - th.y) + inv * (ci.y * p[1] - si.y * q[1]);
            o.z = th.z + om.z + kp.z * (g.z - th.z) + inv * (ci.z * p[2] - si.z * q[2]);
            o.w = th.w + om.w + kp.w * (g.w - th.w) + inv * (ci.w * p[3] - si.w * q[3]);
            out4[row] = o;
        }
    }
}

extern "C" void kernel_launch(void* const* d_in, const int* in_sizes, int n_in,
                              void* d_out, int out_size) {
    (void)in_sizes; (void)n_in; (void)out_size;
    const float4* theta4 = (const float4*)d_in[0];
    const float4* gamma4 = (const float4*)d_in[1];
    const float4* aff4   = (const float4*)d_in[2];
    const float4* alpha4 = (const float4*)d_in[3];
    const float4* omega4 = (const float4*)d_in[4];
    const float4* kappa4 = (const float4*)d_in[5];
    const float4* abias4 = (const float4*)d_in[6];
    float4* out4 = (float4*)d_out;

    static int nsm = 0;
    if (nsm == 0) {
        cudaDeviceProp prop;
        if (cudaGetDeviceProperties(&prop, 0) == cudaSuccess && prop.multiProcessorCount > 0)
            nsm = prop.multiProcessorCount;
        else
            nsm = 148;
        cudaFuncSetAttribute(vector_kuramoto_kernel,
                             cudaFuncAttributeMaxDynamicSharedMemorySize, SMEM_BYTES);
    }

    const int grid = 4 * (nsm / 2);   // 2 CTAs/SM, one uniform wave
    vector_kuramoto_kernel<<<grid, THREADS, SMEM_BYTES>>>(
        theta4, gamma4, aff4, alpha4, omega4, kappa4, abias4, out4);
}

// round 8
// speedup vs baseline: 4.3432x; 1.1349x over previous
#include <cuda_runtime.h>

// VectorKuramoto factorized:
//   sum_j A*sin(tj - ti - a) = ci*P - si*Q
//   P = sum_j (A cos a) sj - (A sin a) cj ; Q = sum_j (A cos a) cj + (A sin a) sj
// R8 = R7's exact one-wave balanced grid (304x512thr, 2 CTAs/SM, warp-granular
// rows) + R2's pair mainloop (2 rows per warp share table reads + double MLP).
// Warps with 2 rows run the pair path; leftover warps run a single-row path.

namespace {

constexpr int Bb = 4;
constexpr int Nn = 2048;
constexpr int N4 = Nn / 4;              // 512 float4 per row
constexpr int THREADS = 512;            // 16 warps

__device__ __host__ __forceinline__ int padidx(int i) { return i + (i >> 3); }
constexpr int PAD_N = Nn + (Nn >> 3);   // 2304 float4 slots per table
constexpr int SMEM_BYTES = 2 * PAD_N * (int)sizeof(float4);  // 73728 B

typedef unsigned long long ull;

#define FMA2(d, a, b, c) \
    asm("fma.rn.f32x2 %0, %1, %2, %3;" : "=l"(d) : "l"(a), "l"(b), "l"(c))
#define PACK2(d, lo, hi) \
    asm("mov.b64 %0, {%1, %2};" : "=l"(d) : "f"(lo), "f"(hi))
#define UNPACK2(lo, hi, s) \
    asm("mov.b64 {%0, %1}, %2;" : "=f"(lo), "=f"(hi) : "l"(s))

union F4U { float4 v; ull u[2]; };

__device__ __forceinline__ void cell(float A, float a,
                                     ull sj01, ull sj23, ull cj01, ull cj23,
                                     ull& Pa, ull& Pb, ull& Qa, ull& Qb)
{
    float sa, ca;
    __sincosf(a, &sa, &ca);
    float w1 = A * ca;
    float w2 = A * sa;
    float nw2 = -w2;
    ull pw1, pw2, pnw2;
    PACK2(pw1, w1, w1);
    PACK2(pw2, w2, w2);
    PACK2(pnw2, nw2, nw2);
    FMA2(Pa, pnw2, cj01, Pa); FMA2(Pa, pw1, sj01, Pa);
    FMA2(Pb, pnw2, cj23, Pb); FMA2(Pb, pw1, sj23, Pb);
    FMA2(Qa, pw2,  sj01, Qa); FMA2(Qa, pw1, cj01, Qa);
    FMA2(Qb, pw2,  sj23, Qb); FMA2(Qb, pw1, cj23, Qb);
}

} // namespace

extern "C" __global__ void __launch_bounds__(THREADS, 2)
vector_kuramoto_kernel(const float4* __restrict__ theta4,
                       const float4* __restrict__ gamma4,
                       const float4* __restrict__ aff4,
                       const float4* __restrict__ alpha4,
                       const float4* __restrict__ omega4,
                       const float4* __restrict__ kappa4,
                       const float4* __restrict__ abias4,
                       float4* __restrict__ out4)
{
    extern __shared__ float4 smem[];
    float4* s4 = smem;            // sin(theta[b,r,:]) at padidx(r)
    float4* c4 = smem + PAD_N;    // cos(theta[b,r,:]) at padidx(r)

    const int K    = gridDim.x >> 2;     // CTAs per batch-group (nsm/2)
    const int b    = blockIdx.x & 3;     // batch for this CTA
    const int rank = blockIdx.x >> 2;    // rank within group

    const int tid  = threadIdx.x;
    const int warp = tid >> 5;
    const int lane = tid & 31;

    // Build per-batch sincos table (theta[b,r,:] is one float4, D=4).
    for (int r = tid; r < Nn; r += THREADS) {
        float4 th = theta4[b * Nn + r];
        float4 s, c;
        __sincosf(th.x, &s.x, &c.x);
        __sincosf(th.y, &s.y, &c.y);
        __sincosf(th.z, &s.z, &c.z);
        __sincosf(th.w, &s.w, &c.w);
        s4[padidx(r)] = s;
        c4[padidx(r)] = c;
    }
    __syncthreads();

    // Warp-granular row assignment (per-SM byte totals flat to ~2%).
    const int wg = warp * K + rank;      // 0 .. 16K-1
    const int S  = K << 4;               // 16K warps per group
    const float inv = 1.0f / (float)Nn;  // COUPLING=1, DT=1

    if (wg >= Nn) return;

    const int i0 = wg;
    const int i1 = wg + S;

    if (i1 < Nn) {
        // ---- Pair path: 2 rows share every table read (16 B/cell LDS). ----
        const int rb0 = ((b << 11) + i0) << 9;   // (b*Nn+i0)*N4
        const int rb1 = ((b << 11) + i1) << 9;
        const int bb0 = i0 << 9;
        const int bb1 = i1 << 9;

        ull P0a = 0, P0b = 0, Q0a = 0, Q0b = 0;
        ull P1a = 0, P1b = 0, Q1a = 0, Q1b = 0;

        #pragma unroll 1
        for (int jb = lane; jb < N4; jb += 32) {
            float4 A0 = __ldcs(aff4   + rb0 + jb);
            float4 T0 = __ldcs(alpha4 + rb0 + jb);
            float4 B0 = abias4[bb0 + jb];
            float4 A1 = __ldcs(aff4   + rb1 + jb);
            float4 T1 = __ldcs(alpha4 + rb1 + jb);
            float4 B1 = abias4[bb1 + jb];

            const int j0 = jb << 2;
            F4U sj, cj;
            sj.v = s4[padidx(j0 + 0)]; cj.v = c4[padidx(j0 + 0)];
            cell(A0.x, T0.x + B0.x, sj.u[0], sj.u[1], cj.u[0], cj.u[1], P0a, P0b, Q0a, Q0b);
            cell(A1.x, T1.x + B1.x, sj.u[0], sj.u[1], cj.u[0], cj.u[1], P1a, P1b, Q1a, Q1b);

            sj.v = s4[padidx(j0 + 1)]; cj.v = c4[padidx(j0 + 1)];
            cell(A0.y, T0.y + B0.y, sj.u[0], sj.u[1], cj.u[0], cj.u[1], P0a, P0b, Q0a, Q0b);
            cell(A1.y, T1.y + B1.y, sj.u[0], sj.u[1], cj.u[0], cj.u[1], P1a, P1b, Q1a, Q1b);

            sj.v = s4[padidx(j0 + 2)]; cj.v = c4[padidx(j0 + 2)];
            cell(A0.z, T0.z + B0.z, sj.u[0], sj.u[1], cj.u[0], cj.u[1], P0a, P0b, Q0a, Q0b);
            cell(A1.z, T1.z + B1.z, sj.u[0], sj.u[1], cj.u[0], cj.u[1], P1a, P1b, Q1a, Q1b);

            sj.v = s4[padidx(j0 + 3)]; cj.v = c4[padidx(j0 + 3)];
            cell(A0.w, T0.w + B0.w, sj.u[0], sj.u[1], cj.u[0], cj.u[1], P0a, P0b, Q0a, Q0b);
            cell(A1.w, T1.w + B1.w, sj.u[0], sj.u[1], cj.u[0], cj.u[1], P1a, P1b, Q1a, Q1b);
        }

        float p0[4], q0[4], p1[4], q1[4];
        UNPACK2(p0[0], p0[1], P0a); UNPACK2(p0[2], p0[3], P0b);
        UNPACK2(q0[0], q0[1], Q0a); UNPACK2(q0[2], q0[3], Q0b);
        UNPACK2(p1[0], p1[1], P1a); UNPACK2(p1[2], p1[3], P1b);
        UNPACK2(q1[0], q1[1], Q1a); UNPACK2(q1[2], q1[3], Q1b);

        #pragma unroll
        for (int off = 16; off; off >>= 1) {
            #pragma unroll
            for (int d = 0; d < 4; ++d) {
                p0[d] += __shfl_down_sync(0xffffffffu, p0[d], off);
                q0[d] += __shfl_down_sync(0xffffffffu, q0[d], off);
                p1[d] += __shfl_down_sync(0xffffffffu, p1[d], off);
                q1[d] += __shfl_down_sync(0xffffffffu, q1[d], off);
            }
        }

        if (lane == 0) {
            {
                const int row = b * Nn + i0;
                float4 th = theta4[row];
                float4 si = s4[padidx(i0)];
                float4 ci = c4[padidx(i0)];
                float4 g  = gamma4[row];
                float4 om = omega4[i0];
                float4 kp = kappa4[i0];
                float4 o;
                o.x = th.x + om.x + kp.x * (g.x - th.x) + inv * (ci.x * p0[0] - si.x * q0[0]);
                o.y = th.y + om.y + kp.y * (g.y - th.y) + inv * (ci.y * p0[1] - si.y * q0[1]);
                o.z = th.z + om.z + kp.z * (g.z - th.z) + inv * (ci.z * p0[2] - si.z * q0[2]);
                o.w = th.w + om.w + kp.w * (g.w - th.w) + inv * (ci.w * p0[3] - si.w * q0[3]);
                out4[row] = o;
            }
            {
                const int row = b * Nn + i1;
                float4 th = theta4[row];
                float4 si = s4[padidx(i1)];
                float4 ci = c4[padidx(i1)];
                float4 g  = gamma4[row];
                float4 om = omega4[i1];
                float4 kp = kappa4[i1];
                float4 o;
                o.x = th.x + om.x + kp.x * (g.x - th.x) + inv * (ci.x * p1[0] - si.x * q1[0]);
                o.y = th.y + om.y + kp.y * (g.y - th.y) + inv * (ci.y * p1[1] - si.y * q1[1]);
                o.z = th.z + om.z + kp.z * (g.z - th.z) + inv * (ci.z * p1[2] - si.z * q1[2]);
                o.w = th.w + om.w + kp.w * (g.w - th.w) + inv * (ci.w * p1[3] - si.w * q1[3]);
                out4[row] = o;
            }
        }
    } else {
        // ---- Single-row path (leftover warps; finish early). ----
        const int row = b * Nn + i0;
        const int rb  = row << 9;
        const int bb  = i0 << 9;

        ull Pa = 0, Pb = 0, Qa = 0, Qb = 0;

        #pragma unroll 1
        for (int jb0 = lane; jb0 < N4; jb0 += 64) {
            const int jb1 = jb0 + 32;
            float4 A0 = __ldcs(aff4   + rb + jb0);
            float4 T0 = __ldcs(alpha4 + rb + jb0);
            float4 A1 = __ldcs(aff4   + rb + jb1);
            float4 T1 = __ldcs(alpha4 + rb + jb1);
            float4 B0 = abias4[bb + jb0];
            float4 B1 = abias4[bb + jb1];

            {
                const int j0 = jb0 << 2;
                F4U sj, cj;
                sj.v = s4[padidx(j0 + 0)]; cj.v = c4[padidx(j0 + 0)];
                cell(A0.x, T0.x + B0.x, sj.u[0], sj.u[1], cj.u[0], cj.u[1], Pa, Pb, Qa, Qb);
                sj.v = s4[padidx(j0 + 1)]; cj.v = c4[padidx(j0 + 1)];
                cell(A0.y, T0.y + B0.y, sj.u[0], sj.u[1], cj.u[0], cj.u[1], Pa, Pb, Qa, Qb);
                sj.v = s4[padidx(j0 + 2)]; cj.v = c4[padidx(j0 + 2)];
                cell(A0.z, T0.z + B0.z, sj.u[0], sj.u[1], cj.u[0], cj.u[1], Pa, Pb, Qa, Qb);
                sj.v = s4[padidx(j0 + 3)]; cj.v = c4[padidx(j0 + 3)];
                cell(A0.w, T0.w + B0.w, sj.u[0], sj.u[1], cj.u[0], cj.u[1], Pa, Pb, Qa, Qb);
            }
            {
                const int j1 = jb1 << 2;
                F4U sj, cj;
                sj.v = s4[padidx(j1 + 0)]; cj.v = c4[padidx(j1 + 0)];
                cell(A1.x, T1.x + B1.x, sj.u[0], sj.u[1], cj.u[0], cj.u[1], Pa, Pb, Qa, Qb);
                sj.v = s4[padidx(j1 + 1)]; cj.v = c4[padidx(j1 + 1)];
                cell(A1.y, T1.y + B1.y, sj.u[0], sj.u[1], cj.u[0], cj.u[1], Pa, Pb, Qa, Qb);
                sj.v = s4[padidx(j1 + 2)]; cj.v = c4[padidx(j1 + 2)];
                cell(A1.z, T1.z + B1.z, sj.u[0], sj.u[1], cj.u[0], cj.u[1], Pa, Pb, Qa, Qb);
                sj.v = s4[padidx(j1 + 3)]; cj.v = c4[padidx(j1 + 3)];
                cell(A1.w, T1.w + B1.w, sj.u[0], sj.u[1], cj.u[0], cj.u[1], Pa, Pb, Qa, Qb);
            }
        }

        float p[4], q[4];
        UNPACK2(p[0], p[1], Pa); UNPACK2(p[2], p[3], Pb);
        UNPACK2(q[0], q[1], Qa); UNPACK2(q[2], q[3], Qb);

        #pragma unroll
        for (int off = 16; off; off >>= 1) {
            #pragma unroll
            for (int d = 0; d < 4; ++d) {
                p[d] += __shfl_down_sync(0xffffffffu, p[d], off);
                q[d] += __shfl_down_sync(0xffffffffu, q[d], off);
            }
        }

        if (lane == 0) {
            float4 th = theta4[row];
            float4 si = s4[padidx(i0)];
            float4 ci = c4[padidx(i0)];
            float4 g  = gamma4[row];
            float4 om = omega4[i0];
            float4 kp = kappa4[i0];
            float4 o;
            o.x = th.x + om.x + kp.x * (g.x - th.x) + inv * (ci.x * p[0] - si.x * q[0]);
            o.y = th.y + om.y + kp.y * (g.y - th.y) + inv * (ci.y * p[1] - si.y * q[1]);
            o.z = th.z + om.z + kp.z * (g.z - th.z) + inv * (ci.z * p[2] - si.z * q[2]);
            o.w = th.w + om.w + kp.w * (g.w - th.w) + inv * (ci.w * p[3] - si.w * q[3]);
            out4[row] = o;
        }
    }
}

extern "C" void kernel_launch(void* const* d_in, const int* in_sizes, int n_in,
                              void* d_out, int out_size) {
    (void)in_sizes; (void)n_in; (void)out_size;
    const float4* theta4 = (const float4*)d_in[0];
    const float4* gamma4 = (const float4*)d_in[1];
    const float4* aff4   = (const float4*)d_in[2];
    const float4* alpha4 = (const float4*)d_in[3];
    const float4* omega4 = (const float4*)d_in[4];
    const float4* kappa4 = (const float4*)d_in[5];
    const float4* abias4 = (const float4*)d_in[6];
    float4* out4 = (float4*)d_out;

    static int nsm = 0;
    if (nsm == 0) {
        cudaDeviceProp prop;
        if (cudaGetDeviceProperties(&prop, 0) == cudaSuccess && prop.multiProcessorCount > 0)
            nsm = prop.multiProcessorCount;
        else
            nsm = 148;
        cudaFuncSetAttribute(vector_kuramoto_kernel,
                             cudaFuncAttributeMaxDynamicSharedMemorySize, SMEM_BYTES);
    }

    const int grid = 4 * (nsm / 2);   // 2 CTAs/SM, one uniform wave
    vector_kuramoto_kernel<<<grid, THREADS, SMEM_BYTES>>>(
        theta4, gamma4, aff4, alpha4, omega4, kappa4, abias4, out4);
}